// round 2
// baseline (speedup 1.0000x reference)
#include <cuda_runtime.h>
#include <cstdint>

// out = sum_{b, k != labels[b]} exp( -||inputs[b,:] - decoded[b,k,:]||^2 )
// B=4096, K=64, DIM=512, fp32. Pure HBM stream over decoded (512 MiB).
//
// Strategy: dynamic warp-level work queue (kills wave-quantization tail),
// 2-row load interleave (MLP=8 per warp), inputs row in registers.

#define B_    4096
#define K_    64
#define DIM_  512
#define KG_   8                         // k-rows per work unit
#define NUNITS_ (B_ * (K_ / KG_))       // 32768 units

__device__ int g_unit_counter;

__global__ void init_kernel(float* out) {
    if (threadIdx.x == 0) {
        out[0] = 0.0f;
        g_unit_counter = 0;
    }
}

__global__ __launch_bounds__(256)
void mse_exp_loss_kernel(const float* __restrict__ inputs,
                         const float* __restrict__ decoded,
                         const long long* __restrict__ labels,
                         float* __restrict__ out) {
    const int lane = threadIdx.x & 31;
    float acc = 0.0f;

    for (;;) {
        // warp leader grabs the next work unit
        int u;
        if (lane == 0) u = atomicAdd(&g_unit_counter, 1);
        u = __shfl_sync(0xFFFFFFFFu, u, 0);
        if (u >= NUNITS_) break;

        const int b  = u >> 3;          // K_/KG_ = 8 units per batch row
        const int k0 = (u & 7) * KG_;
        const int lbl = (int)__ldg(&labels[b]);

        // stage inputs[b] in registers: 16 floats per lane (reused 8x)
        const float4* inrow = reinterpret_cast<const float4*>(
            inputs + (size_t)b * DIM_);
        float4 x[4];
        #pragma unroll
        for (int i = 0; i < 4; i++) x[i] = __ldg(&inrow[lane + i * 32]);

        const float4* dbase = reinterpret_cast<const float4*>(
            decoded + ((size_t)b * K_ + k0) * DIM_);

        #pragma unroll
        for (int kk = 0; kk < KG_; kk += 2) {
            const float4* r0 = dbase + (kk    ) * (DIM_ / 4);
            const float4* r1 = dbase + (kk + 1) * (DIM_ / 4);

            // issue all 8 streaming loads before consuming (MLP=8)
            float4 d0[4], d1[4];
            #pragma unroll
            for (int i = 0; i < 4; i++) d0[i] = __ldcs(&r0[lane + i * 32]);
            #pragma unroll
            for (int i = 0; i < 4; i++) d1[i] = __ldcs(&r1[lane + i * 32]);

            float s0 = 0.0f, s1 = 0.0f;
            #pragma unroll
            for (int i = 0; i < 4; i++) {
                float e;
                e = x[i].x - d0[i].x; s0 = fmaf(e, e, s0);
                e = x[i].y - d0[i].y; s0 = fmaf(e, e, s0);
                e = x[i].z - d0[i].z; s0 = fmaf(e, e, s0);
                e = x[i].w - d0[i].w; s0 = fmaf(e, e, s0);
                e = x[i].x - d1[i].x; s1 = fmaf(e, e, s1);
                e = x[i].y - d1[i].y; s1 = fmaf(e, e, s1);
                e = x[i].z - d1[i].z; s1 = fmaf(e, e, s1);
                e = x[i].w - d1[i].w; s1 = fmaf(e, e, s1);
            }

            // two independent butterfly reductions (latencies overlap)
            #pragma unroll
            for (int o = 16; o > 0; o >>= 1) {
                s0 += __shfl_xor_sync(0xFFFFFFFFu, s0, o);
                s1 += __shfl_xor_sync(0xFFFFFFFFu, s1, o);
            }

            if (lane == 0) {
                if (k0 + kk     != lbl) acc += __expf(-s0);
                if (k0 + kk + 1 != lbl) acc += __expf(-s1);
            }
        }
    }

    if (lane == 0 && acc != 0.0f)
        atomicAdd(out, acc);
    else if (lane == 0)
        atomicAdd(out, acc);   // keep unconditional add semantics (acc may be +0)
}

extern "C" void kernel_launch(void* const* d_in, const int* in_sizes, int n_in,
                              void* d_out, int out_size) {
    const float*     inputs  = (const float*)d_in[0];
    const float*     decoded = (const float*)d_in[1];
    const long long* labels  = (const long long*)d_in[2];
    float* out = (float*)d_out;

    init_kernel<<<1, 32>>>(out);
    // 8 CTAs per SM target; extra CTAs beyond residency just drain the queue.
    mse_exp_loss_kernel<<<1216, 256>>>(inputs, decoded, labels, out);
}

// round 3
// speedup vs baseline: 1.1637x; 1.1637x over previous
#include <cuda_runtime.h>
#include <cstdint>

// out = sum_{b, k != labels[b]} exp( -||inputs[b,:] - decoded[b,k,:]||^2 )
// B=4096, K=64, DIM=512, fp32. Pure HBM stream over decoded (512 MiB).
//
// Single-wave static launch: 4096 CTAs x 64 threads (27 CTAs/SM resident,
// no wave-quantization tail). 2 warps/CTA, 32 k-rows per warp, inputs row
// register-staged once per warp, 2-row load interleave (8 outstanding
// LDG.128 per warp).

#define B_    4096
#define K_    64
#define DIM_  512

__global__ void init_kernel(float* out) {
    if (threadIdx.x == 0) out[0] = 0.0f;
}

__global__ __launch_bounds__(64, 28)
void mse_exp_loss_kernel(const float* __restrict__ inputs,
                         const float* __restrict__ decoded,
                         const long long* __restrict__ labels,
                         float* __restrict__ out) {
    const int b    = blockIdx.x;
    const int warp = threadIdx.x >> 5;         // 0..1
    const int lane = threadIdx.x & 31;
    const int k0   = warp * 32;                // this warp's 32 k-rows
    const int lbl  = (int)__ldg(&labels[b]);

    // stage inputs[b] in registers: 16 floats/lane, reused for all 32 rows
    const float4* inrow = reinterpret_cast<const float4*>(
        inputs + (size_t)b * DIM_);
    float4 x[4];
    #pragma unroll
    for (int i = 0; i < 4; i++) x[i] = __ldg(&inrow[lane + i * 32]);

    const float4* dbase = reinterpret_cast<const float4*>(
        decoded + ((size_t)b * K_ + k0) * DIM_);

    float acc = 0.0f;

    #pragma unroll
    for (int kk = 0; kk < 32; kk += 2) {
        const float4* r0 = dbase + (kk    ) * (DIM_ / 4);
        const float4* r1 = dbase + (kk + 1) * (DIM_ / 4);

        // issue 8 independent streaming loads before consuming (MLP=8)
        float4 d0[4], d1[4];
        #pragma unroll
        for (int i = 0; i < 4; i++) d0[i] = __ldcs(&r0[lane + i * 32]);
        #pragma unroll
        for (int i = 0; i < 4; i++) d1[i] = __ldcs(&r1[lane + i * 32]);

        float s0 = 0.0f, s1 = 0.0f;
        #pragma unroll
        for (int i = 0; i < 4; i++) {
            float e;
            e = x[i].x - d0[i].x; s0 = fmaf(e, e, s0);
            e = x[i].y - d0[i].y; s0 = fmaf(e, e, s0);
            e = x[i].z - d0[i].z; s0 = fmaf(e, e, s0);
            e = x[i].w - d0[i].w; s0 = fmaf(e, e, s0);
            e = x[i].x - d1[i].x; s1 = fmaf(e, e, s1);
            e = x[i].y - d1[i].y; s1 = fmaf(e, e, s1);
            e = x[i].z - d1[i].z; s1 = fmaf(e, e, s1);
            e = x[i].w - d1[i].w; s1 = fmaf(e, e, s1);
        }

        // two independent butterfly reductions (latencies overlap)
        #pragma unroll
        for (int o = 16; o > 0; o >>= 1) {
            s0 += __shfl_xor_sync(0xFFFFFFFFu, s0, o);
            s1 += __shfl_xor_sync(0xFFFFFFFFu, s1, o);
        }

        if (lane == 0) {
            if (k0 + kk     != lbl) acc += __expf(-s0);
            if (k0 + kk + 1 != lbl) acc += __expf(-s1);
        }
    }

    // exp(-s) with s ~ 1024 underflows to +0; skipping a +0 add is exact and
    // avoids 8192 same-address L2 atomics all landing at end-of-wave.
    if (lane == 0 && acc != 0.0f)
        atomicAdd(out, acc);
}

extern "C" void kernel_launch(void* const* d_in, const int* in_sizes, int n_in,
                              void* d_out, int out_size) {
    const float*     inputs  = (const float*)d_in[0];
    const float*     decoded = (const float*)d_in[1];
    const long long* labels  = (const long long*)d_in[2];
    float* out = (float*)d_out;

    init_kernel<<<1, 32>>>(out);
    mse_exp_loss_kernel<<<B_, 64>>>(inputs, decoded, labels, out);
}

// round 4
// speedup vs baseline: 1.2531x; 1.0768x over previous
#include <cuda_runtime.h>
#include <cstdint>

// out = sum_{b, k != labels[b]} exp( -||inputs[b,:] - decoded[b,k,:]||^2 )
// B=4096, K=64, DIM=512, fp32. Pure HBM stream over decoded (512 MiB).
//
// Grid = 8192 CTAs x 64 threads: each CTA handles HALF a batch row
// (2 warps x 16 k-rows). 32 CTAs/SM resident (full occupancy); ~1.7
// allocation waves with hardware work-steal -> fine-grained finish tail
// instead of one ragged single-wave edge.

#define B_    4096
#define K_    64
#define DIM_  512

__global__ void init_kernel(float* out) {
    if (threadIdx.x == 0) out[0] = 0.0f;
}

__global__ __launch_bounds__(64)
void mse_exp_loss_kernel(const float* __restrict__ inputs,
                         const float* __restrict__ decoded,
                         const long long* __restrict__ labels,
                         float* __restrict__ out) {
    const int b    = blockIdx.x >> 1;           // 2 CTAs per batch row
    const int half = blockIdx.x & 1;
    const int warp = threadIdx.x >> 5;          // 0..1
    const int lane = threadIdx.x & 31;
    const int k0   = half * 32 + warp * 16;     // this warp's 16 k-rows
    const int lbl  = (int)__ldg(&labels[b]);

    // stage inputs[b] in registers: 16 floats/lane, reused for 16 rows
    const float4* inrow = reinterpret_cast<const float4*>(
        inputs + (size_t)b * DIM_);
    float4 x[4];
    #pragma unroll
    for (int i = 0; i < 4; i++) x[i] = __ldg(&inrow[lane + i * 32]);

    const float4* dbase = reinterpret_cast<const float4*>(
        decoded + ((size_t)b * K_ + k0) * DIM_);

    float acc = 0.0f;

    #pragma unroll
    for (int kk = 0; kk < 16; kk += 2) {
        const float4* r0 = dbase + (kk    ) * (DIM_ / 4);
        const float4* r1 = dbase + (kk + 1) * (DIM_ / 4);

        // issue 8 independent streaming loads before consuming
        float4 d0[4], d1[4];
        #pragma unroll
        for (int i = 0; i < 4; i++) d0[i] = __ldcs(&r0[lane + i * 32]);
        #pragma unroll
        for (int i = 0; i < 4; i++) d1[i] = __ldcs(&r1[lane + i * 32]);

        float s0 = 0.0f, s1 = 0.0f;
        #pragma unroll
        for (int i = 0; i < 4; i++) {
            float e;
            e = x[i].x - d0[i].x; s0 = fmaf(e, e, s0);
            e = x[i].y - d0[i].y; s0 = fmaf(e, e, s0);
            e = x[i].z - d0[i].z; s0 = fmaf(e, e, s0);
            e = x[i].w - d0[i].w; s0 = fmaf(e, e, s0);
            e = x[i].x - d1[i].x; s1 = fmaf(e, e, s1);
            e = x[i].y - d1[i].y; s1 = fmaf(e, e, s1);
            e = x[i].z - d1[i].z; s1 = fmaf(e, e, s1);
            e = x[i].w - d1[i].w; s1 = fmaf(e, e, s1);
        }

        // two independent butterfly reductions (latencies overlap)
        #pragma unroll
        for (int o = 16; o > 0; o >>= 1) {
            s0 += __shfl_xor_sync(0xFFFFFFFFu, s0, o);
            s1 += __shfl_xor_sync(0xFFFFFFFFu, s1, o);
        }

        if (lane == 0) {
            if (k0 + kk     != lbl) acc += __expf(-s0);
            if (k0 + kk + 1 != lbl) acc += __expf(-s1);
        }
    }

    // exp(-s) with s ~ 1024 underflows to +0; skipping a +0 add is exact and
    // avoids 16384 same-address L2 atomics bunching at the end.
    if (lane == 0 && acc != 0.0f)
        atomicAdd(out, acc);
}

extern "C" void kernel_launch(void* const* d_in, const int* in_sizes, int n_in,
                              void* d_out, int out_size) {
    const float*     inputs  = (const float*)d_in[0];
    const float*     decoded = (const float*)d_in[1];
    const long long* labels  = (const long long*)d_in[2];
    float* out = (float*)d_out;

    init_kernel<<<1, 32>>>(out);
    mse_exp_loss_kernel<<<B_ * 2, 64>>>(inputs, decoded, labels, out);
}